// round 6
// baseline (speedup 1.0000x reference)
#include <cuda_runtime.h>
#include <cuda_bf16.h>

// ---------------------------------------------------------------------------
// HardTripletMiningLoss  (n=3B=480, D=128)
//   gram = E E^T ;  pd[i,j] = max(sq_i + sq_j - 2 gram_ij, 0)
//   loss = mean over {i!=0, lab[i]==lab[j], lab[k]!=lab[j], td>0} of
//          td = pd[i,j] - pd[j,k] + A
// R6: gram-based pd (pure-FMA inner loop, half the flops of diff form),
//     48x48 tile / 3x3 per thread / 256 thr -> 100 blocks = ONE wave.
//     Triplet reconstructs pdrow from gram row + norms in smem.
// ---------------------------------------------------------------------------

#define MAX_N    768
#define MAXW     ((MAX_N + 31) / 32)
#define POSCAP   128
#define MARGIN_A 0.2f
#define TM       48
#define DS       129   // odd stride -> conflict-free 3-row fan-out (gcd(3,32)=1)

static __device__ float g_gram[MAX_N * MAX_N];
static __device__ float g_sq[MAX_N];
static __device__ float g_ps[MAX_N];
static __device__ int   g_pc[MAX_N];

__device__ __forceinline__ const float* row_ptr(const float* a, const float* p,
                                                const float* ng, int r, int B, int D) {
    if (r < B)      return a  + (size_t)r * D;
    if (r < 2 * B)  return p  + (size_t)(r - B) * D;
    return ng + (size_t)(r - 2 * B) * D;
}

// ---------------------------------------------------------------------------
// gram kernel: grid (n/48, n/48), 256 threads, 48x48 tile, 3x3 per thread.
// Inner loop per k: 6 LDS + 9 FMA. Diagonal threads also emit g_sq.
// ---------------------------------------------------------------------------
__global__ void gram_kernel(const float* __restrict__ anchor,
                            const float* __restrict__ positive,
                            const float* __restrict__ negative,
                            int n, int B, int D) {
    __shared__ float As[TM][DS];
    __shared__ float Bs[TM][DS];

    const int bi  = blockIdx.y * TM;
    const int bj  = blockIdx.x * TM;
    const int tid = threadIdx.x;

    const int nf4 = D >> 2;                       // 32 for D=128
    for (int idx = tid; idx < TM * nf4; idx += 256) {
        const int r  = idx / nf4;
        const int c4 = idx - r * nf4;
        const int ra = (bi + r < n) ? bi + r : n - 1;
        const int rb = (bj + r < n) ? bj + r : n - 1;
        const float4 va = ((const float4*)row_ptr(anchor, positive, negative, ra, B, D))[c4];
        As[r][c4 * 4 + 0] = va.x; As[r][c4 * 4 + 1] = va.y;
        As[r][c4 * 4 + 2] = va.z; As[r][c4 * 4 + 3] = va.w;
        const float4 vb = ((const float4*)row_ptr(anchor, positive, negative, rb, B, D))[c4];
        Bs[r][c4 * 4 + 0] = vb.x; Bs[r][c4 * 4 + 1] = vb.y;
        Bs[r][c4 * 4 + 2] = vb.z; Bs[r][c4 * 4 + 3] = vb.w;
    }
    __syncthreads();

    const int tx = tid & 15;
    const int ty = tid >> 4;
    const int r0 = ty * 3;
    const int c0 = tx * 3;

    float acc[3][3];
    #pragma unroll
    for (int i = 0; i < 3; i++)
        #pragma unroll
        for (int q = 0; q < 3; q++) acc[i][q] = 0.f;

    #pragma unroll 4
    for (int k = 0; k < D; k++) {
        float av[3], bv[3];
        #pragma unroll
        for (int i = 0; i < 3; i++) av[i] = As[r0 + i][k];
        #pragma unroll
        for (int q = 0; q < 3; q++) bv[q] = Bs[c0 + q][k];
        #pragma unroll
        for (int i = 0; i < 3; i++)
            #pragma unroll
            for (int q = 0; q < 3; q++)
                acc[i][q] = fmaf(av[i], bv[q], acc[i][q]);
    }

    #pragma unroll
    for (int i = 0; i < 3; i++) {
        const int gi = bi + r0 + i;
        if (gi >= n) continue;
        const size_t rowoff = (size_t)gi * n;
        #pragma unroll
        for (int q = 0; q < 3; q++) {
            const int gj = bj + c0 + q;
            if (gj < n) {
                g_gram[rowoff + gj] = acc[i][q];
                if (gi == gj) g_sq[gi] = acc[i][q];
            }
        }
    }
}

// ---------------------------------------------------------------------------
// Triplet: one block (128 thr) per j. Reconstruct pdrow from gram row + sq,
// ballot compaction, branch-free fp32 hot loop, (float,int) partials out.
// ---------------------------------------------------------------------------
__global__ void triplet_kernel(const int* __restrict__ ind, int n) {
    __shared__ float    pdrow[MAX_N];
    __shared__ float    sq_s[MAX_N];
    __shared__ int      labs[MAX_N];
    __shared__ float    avals[POSCAP];
    __shared__ unsigned chunkMask[MAXW];
    __shared__ int      chunkOff[MAXW];
    __shared__ int      nSame;
    __shared__ float    red_s[4];
    __shared__ int      red_c[4];

    const int j    = blockIdx.x;
    const int tid  = threadIdx.x;
    const int lane = tid & 31;
    const int wid  = tid >> 5;

    // load gram row j (raw) + norms + labels
    const float* rowp = g_gram + (size_t)j * n;
    const int n4 = n >> 2;
    for (int v = tid; v < n4; v += 128) {
        ((float4*)pdrow)[v] = ((const float4*)rowp)[v];
        ((float4*)sq_s)[v]  = ((const float4*)g_sq)[v];
    }
    for (int v = (n4 << 2) + tid; v < n; v += 128) {
        pdrow[v] = rowp[v];
        sq_s[v]  = g_sq[v];
    }
    for (int t = tid; t < n; t += 128)
        labs[t] = ind[t];
    __syncthreads();

    // reconstruct pd row: pd = max(sq_j + sq_t - 2*gram, 0)
    const float sqj = sq_s[j];
    for (int t = tid; t < n; t += 128)
        pdrow[t] = fmaxf(fmaf(-2.f, pdrow[t], sqj + sq_s[t]), 0.f);
    __syncthreads();

    const int labj = labs[j];

    // ballot compaction of same-label i's (i != 0), deterministic order
    const int nChunks = (n + 31) >> 5;
    for (int c = wid; c < nChunks; c += 4) {
        const int t = (c << 5) + lane;
        const bool pred = (t < n) && (t != 0) && (labs[t] == labj);
        const unsigned m = __ballot_sync(0xffffffffu, pred);
        if (lane == 0) chunkMask[c] = m;
    }
    __syncthreads();
    if (tid == 0) {
        int off = 0;
        for (int c = 0; c < nChunks; c++) { chunkOff[c] = off; off += __popc(chunkMask[c]); }
        nSame = off;
    }
    __syncthreads();
    for (int c = wid; c < nChunks; c += 4) {
        const unsigned m = chunkMask[c];
        const int t = (c << 5) + lane;
        if ((m >> lane) & 1u)
            avals[chunkOff[c] + __popc(m & ((1u << lane) - 1u))] = pdrow[t] + MARGIN_A;
    }
    __syncthreads();

    // this thread's diff-label pd values in 4 register slots
    float pdk[4];
    #pragma unroll
    for (int m = 0; m < 4; m++) pdk[m] = 3.4e38f;   // sentinel: never counted
    {
        int m = 0;
        for (int k = tid; k < n; k += 128, m++)
            if (labs[k] != labj) pdk[m] = pdrow[k];
    }

    // hot loop
    const int ns = nSame;
    float s = 0.f;
    int   c = 0;
    for (int q = 0; q < ns; q++) {
        const float aq = avals[q];
        #pragma unroll
        for (int m = 0; m < 4; m++) {
            const float v = aq - pdk[m];
            if (v > 0.f) { s += v; c++; }
        }
    }

    #pragma unroll
    for (int o = 16; o > 0; o >>= 1) {
        s += __shfl_down_sync(0xffffffffu, s, o);
        c += __shfl_down_sync(0xffffffffu, c, o);
    }
    if (lane == 0) { red_s[wid] = s; red_c[wid] = c; }
    __syncthreads();
    if (tid == 0) {
        float st = 0.f; int ct = 0;
        #pragma unroll
        for (int w = 0; w < 4; w++) { st += red_s[w]; ct += red_c[w]; }
        g_ps[j] = st;
        g_pc[j] = ct;
    }
}

// ---------------------------------------------------------------------------
// Final: single block, fp64 reduce of n partials.
// ---------------------------------------------------------------------------
__global__ void final_kernel(float* __restrict__ out, int n) {
    __shared__ double red_s[4];
    __shared__ double red_c[4];
    const int tid  = threadIdx.x;
    const int lane = tid & 31;
    const int wid  = tid >> 5;

    double s = 0.0, c = 0.0;
    for (int t = tid; t < n; t += 128) { s += (double)g_ps[t]; c += (double)g_pc[t]; }
    #pragma unroll
    for (int o = 16; o > 0; o >>= 1) {
        s += __shfl_down_sync(0xffffffffu, s, o);
        c += __shfl_down_sync(0xffffffffu, c, o);
    }
    if (lane == 0) { red_s[wid] = s; red_c[wid] = c; }
    __syncthreads();
    if (tid == 0) {
        double st = 0.0, ct = 0.0;
        #pragma unroll
        for (int w = 0; w < 4; w++) { st += red_s[w]; ct += red_c[w]; }
        out[0] = (ct > 0.0) ? (float)(st / (ct < 1.0 ? 1.0 : ct)) : 0.0f;
    }
}

extern "C" void kernel_launch(void* const* d_in, const int* in_sizes, int n_in,
                              void* d_out, int out_size) {
    const float* anchor   = (const float*)d_in[0];
    const float* positive = (const float*)d_in[1];
    const float* negative = (const float*)d_in[2];
    const int*   ind      = (const int*)d_in[3];

    const int n = in_sizes[3];          // 3B
    const int B = n / 3;
    const int D = in_sizes[0] / B;

    dim3 grid((n + TM - 1) / TM, (n + TM - 1) / TM);   // 10x10 = 100 blocks = 1 wave
    gram_kernel<<<grid, 256>>>(anchor, positive, negative, n, B, D);
    triplet_kernel<<<n, 128>>>(ind, n);
    final_kernel<<<1, 128>>>((float*)d_out, n);
}